// round 3
// baseline (speedup 1.0000x reference)
#include <cuda_runtime.h>
#include <cuda_bf16.h>
#include <cstdint>

// ---------------- problem constants ----------------
#define NPTS   512            // batch N
#define TT     300            // time steps
#define FF     150            // feature dim
#define HH     100            // hidden dim
#define G4     400            // 4*H gate rows
// x layout strides (floats): x[n][c][t][v][m], C=3,V=25,M=2
#define XSTR_N 45000
#define XSTR_C 15000
#define XSTR_T 50

// ---------------- scratch (device globals; no allocs allowed) ----------------
__device__ float g_Xp[(size_t)TT * NPTS * G4];       // 61.44M floats: encoder pre-activations (+bias)
__device__ float g_Hs[(size_t)(TT - 1) * NPTS * HH]; // 15.3M floats: decoder hidden states
__device__ float g_Wt[FF * G4];                      // enc_Wih transposed [f][g]
__device__ float g_Wd[G4 * HH];                      // folded decoder recurrent matrix
__device__ float g_biase[G4];
__device__ float g_bias0[G4];
__device__ float g_biasd[G4];

// ---------------- helpers ----------------
__device__ __forceinline__ void ffma2(float2& c, const float2& a, const float2& b) {
    asm("fma.rn.f32x2 %0, %1, %2, %0;"
        : "+l"(reinterpret_cast<unsigned long long&>(c))
        : "l"(reinterpret_cast<const unsigned long long&>(a)),
          "l"(reinterpret_cast<const unsigned long long&>(b)));
}

__device__ __forceinline__ float sigm(float x) {
    return __fdividef(1.0f, 1.0f + __expf(-x));
}
__device__ __forceinline__ float tanh_(float x) {
    return __fdividef(2.0f, 1.0f + __expf(-2.0f * x)) - 1.0f;
}

// ---------------- prep 1: transpose enc_Wih, build biases ----------------
__global__ void prep_misc_kernel(const float* __restrict__ encWih,
                                 const float* __restrict__ encbih,
                                 const float* __restrict__ encbhh,
                                 const float* __restrict__ decWih,
                                 const float* __restrict__ decbih,
                                 const float* __restrict__ decbhh,
                                 const float* __restrict__ fcb) {
    const int gg  = blockIdx.x;   // gate row 0..399
    const int tid = threadIdx.x;  // 160 threads
    if (tid < FF) g_Wt[tid * G4 + gg] = encWih[gg * FF + tid];
    __shared__ float red[160];
    red[tid] = (tid < FF) ? decWih[gg * FF + tid] * fcb[tid] : 0.0f;
    __syncthreads();
    if (tid == 0) {
        float sum = 0.0f;
        for (int f = 0; f < FF; f++) sum += red[f];
        g_biase[gg] = encbih[gg] + encbhh[gg];
        float b0 = decbih[gg] + decbhh[gg];
        g_bias0[gg] = b0;
        g_biasd[gg] = b0 + sum;
    }
}

// ---------------- prep 2: Wd = dec_Whh + dec_Wih @ fc_W ----------------
__global__ void prep_wd_kernel(const float* __restrict__ decWih,
                               const float* __restrict__ decWhh,
                               const float* __restrict__ fcW) {
    const int gg = blockIdx.x;   // 0..399
    const int h  = threadIdx.x;  // 128 threads
    if (h < HH) {
        float acc = decWhh[gg * HH + h];
        for (int f = 0; f < FF; f++)
            acc += decWih[gg * FF + f] * fcW[f * HH + h];
        g_Wd[gg * HH + h] = acc;
    }
}

// ---------------- xproj: Xp[t*512+n][g] = xs[n,t,:] @ enc_Wih[g,:].T + biase[g] ----------------
// Tile: 40 nt-rows x 400 g per block. 256 threads (250 active: gi=tid%25, ni=tid/25).
// Smem: Adup (A values duplicated into float2 lanes) [150][41] float2 + Ws k-chunk [25][400] float.
#define XP_NT   40
#define XP_NTP  41
#define XP_KC   25
#define XP_SMEM (150 * XP_NTP * 8 + XP_KC * G4 * 4)  // 49200 + 40000 = 89200 B

__global__ void __launch_bounds__(256, 2) xproj_kernel(const float* __restrict__ x) {
    extern __shared__ float sm[];
    float2* Adup = reinterpret_cast<float2*>(sm);   // [150][XP_NTP]
    float*  Ws   = sm + 150 * XP_NTP * 2;           // [XP_KC][400]

    const int tid = threadIdx.x;
    const int nt0 = blockIdx.x * XP_NT;

    // stage A (x gather), duplicated into both f32x2 lanes
    for (int idx = tid; idx < XP_NT * FF; idx += 256) {
        int row = idx / FF, f = idx % FF;
        int nt = nt0 + row;
        int n = nt & 511, t = nt >> 9;
        float v = x[(size_t)n * XSTR_N + (f / 50) * XSTR_C + t * XSTR_T + (f % 50)];
        Adup[f * XP_NTP + row] = make_float2(v, v);
    }

    const bool act = tid < 250;
    const int gi = tid % 25;   // g-pair base: g = 2*gi + 50*j
    const int ni = tid / 25;   // nt rows ni*4 .. ni*4+3

    float2 acc[4][8];
    #pragma unroll
    for (int r = 0; r < 4; r++)
        #pragma unroll
        for (int j = 0; j < 8; j++) acc[r][j] = make_float2(0.f, 0.f);

    for (int kc = 0; kc < FF; kc += XP_KC) {
        __syncthreads();   // A staged / previous Ws consumed
        for (int idx = tid; idx < XP_KC * G4; idx += 256)
            Ws[idx] = g_Wt[kc * G4 + idx];
        __syncthreads();
        if (act) {
            #pragma unroll
            for (int k = 0; k < XP_KC; k++) {
                float2 a0 = Adup[(kc + k) * XP_NTP + ni * 4 + 0];
                float2 a1 = Adup[(kc + k) * XP_NTP + ni * 4 + 1];
                float2 a2 = Adup[(kc + k) * XP_NTP + ni * 4 + 2];
                float2 a3 = Adup[(kc + k) * XP_NTP + ni * 4 + 3];
                #pragma unroll
                for (int j = 0; j < 8; j++) {
                    float2 w = *reinterpret_cast<const float2*>(&Ws[k * G4 + 2 * gi + 50 * j]);
                    ffma2(acc[0][j], a0, w);
                    ffma2(acc[1][j], a1, w);
                    ffma2(acc[2][j], a2, w);
                    ffma2(acc[3][j], a3, w);
                }
            }
        }
    }

    if (act) {
        #pragma unroll
        for (int r = 0; r < 4; r++) {
            size_t base = (size_t)(nt0 + ni * 4 + r) * G4;
            #pragma unroll
            for (int j = 0; j < 8; j++) {
                int gg = 2 * gi + 50 * j;
                float2 o = acc[r][j];
                o.x += g_biase[gg];
                o.y += g_biasd == nullptr ? 0.f : g_biase[gg + 1]; // (kept simple; see below)
                *reinterpret_cast<float2*>(&g_Xp[base + gg]) = o;
            }
        }
    }
}

// ---------------- recurrence: 128 CTAs x 4 samples, 599 serial steps ----------------
__global__ void __launch_bounds__(416, 1) recur_kernel(const float* __restrict__ encWhh,
                                                       const float* __restrict__ decWhh) {
    __shared__ float Hsm[4][104];
    __shared__ float Gsm[4][G4];

    const int tid = threadIdx.x;
    const bool act = tid < G4;
    const int gate = tid;            // gate row (if act)
    const int s = (tid < G4) ? (tid / HH) : 0;  // sample slot for update phase
    const int j = tid % HH;                      // hidden unit for update phase
    const int n0 = blockIdx.x * 4;

    float2 W2[50];
    float creg = 0.0f;

    // init h = 0 (4*104 = 416 == blockDim)
    reinterpret_cast<float*>(Hsm)[tid] = 0.0f;

    if (act) {
        const float2* wr = reinterpret_cast<const float2*>(encWhh + gate * HH);
        #pragma unroll
        for (int k2 = 0; k2 < 50; k2++) W2[k2] = wr[k2];
    }
    __syncthreads();

    auto matvec = [&](float2& a0, float2& a1, float2& a2, float2& a3) {
        #pragma unroll
        for (int k2 = 0; k2 < 50; k2++) {
            float2 w = W2[k2];
            ffma2(a0, w, *reinterpret_cast<const float2*>(&Hsm[0][2 * k2]));
            ffma2(a1, w, *reinterpret_cast<const float2*>(&Hsm[1][2 * k2]));
            ffma2(a2, w, *reinterpret_cast<const float2*>(&Hsm[2][2 * k2]));
            ffma2(a3, w, *reinterpret_cast<const float2*>(&Hsm[3][2 * k2]));
        }
    };

    auto step = [&](float x0, float x1, float x2, float x3, bool store_h, int k) {
        if (act) {
            float2 a0 = make_float2(0.f, 0.f), a1 = a0, a2 = a0, a3 = a0;
            matvec(a0, a1, a2, a3);
            float p0 = a0.x + a0.y + x0;
            float p1 = a1.x + a1.y + x1;
            float p2 = a2.x + a2.y + x2;
            float p3 = a3.x + a3.y + x3;
            if (gate >= 200 && gate < 300) {  // g-gate: tanh
                Gsm[0][gate] = tanh_(p0); Gsm[1][gate] = tanh_(p1);
                Gsm[2][gate] = tanh_(p2); Gsm[3][gate] = tanh_(p3);
            } else {                           // i, f, o: sigmoid
                Gsm[0][gate] = sigm(p0); Gsm[1][gate] = sigm(p1);
                Gsm[2][gate] = sigm(p2); Gsm[3][gate] = sigm(p3);
            }
        }
        __syncthreads();
        if (act) {
            float i_ = Gsm[s][j];
            float f_ = Gsm[s][HH + j];
            float gg = Gsm[s][2 * HH + j];
            float o_ = Gsm[s][3 * HH + j];
            creg = f_ * creg + i_ * gg;
            float hn = o_ * tanh_(creg);
            Hsm[s][j] = hn;
            if (store_h)
                g_Hs[((size_t)k * NPTS + n0 + s) * HH + j] = hn;
        }
        __syncthreads();
    };

    // ---- encoder: 300 steps ----
    for (int t = 0; t < TT; t++) {
        float x0 = 0.f, x1 = 0.f, x2 = 0.f, x3 = 0.f;
        if (act) {
            const float* xp = g_Xp + ((size_t)t * NPTS + n0) * G4 + gate;
            x0 = xp[0]; x1 = xp[G4]; x2 = xp[2 * G4]; x3 = xp[3 * G4];
        }
        step(x0, x1, x2, x3, false, 0);
    }

    // ---- decoder step 0: raw dec_Whh (inp = 0) ----
    if (act) {
        const float2* wr = reinterpret_cast<const float2*>(decWhh + gate * HH);
        #pragma unroll
        for (int k2 = 0; k2 < 50; k2++) W2[k2] = wr[k2];
    }
    {
        float b = act ? g_bias0[gate] : 0.f;
        step(b, b, b, b, true, 0);
    }

    // ---- decoder steps 1..298: folded Wd ----
    if (act) {
        const float2* wr = reinterpret_cast<const float2*>(g_Wd + gate * HH);
        #pragma unroll
        for (int k2 = 0; k2 < 50; k2++) W2[k2] = wr[k2];
    }
    {
        float b = act ? g_biasd[gate] : 0.f;
        for (int k = 1; k < TT - 1; k++)
            step(b, b, b, b, true, k);
    }
}

// ---------------- zero out t=0 slice of the output ----------------
__global__ void zero_t0_kernel(float* __restrict__ out) {
    int idx = blockIdx.x * 256 + threadIdx.x;
    if (idx < NPTS * FF) {
        int n = idx / FF, f = idx % FF;
        out[(size_t)n * XSTR_N + (f / 50) * XSTR_C + (f % 50)] = 0.0f;
    }
}

// ---------------- fc: out[t>=1] = Hs @ fc_W.T + fc_b, scattered to (N,C,T,V,M) ----------------
// Block: 16 rows (flat d = k*512+n) x 150 f. 160 threads, 150 active:
//   rg = tid/75 (row-group of 8), f = 2*(tid%75). FFMA2 paired over h.
#define FC_ROWS 16
#define FC_WPAD 102
#define FC_SMEM ((FF * FC_WPAD + FC_ROWS * HH) * 4)  // 61200 + 6400 = 67600 B

__global__ void fc_kernel(const float* __restrict__ fcW,
                          const float* __restrict__ fcb,
                          float* __restrict__ out) {
    extern __shared__ float sm[];
    float* fcWs = sm;                 // [150][FC_WPAD]
    float* hs   = sm + FF * FC_WPAD;  // [16][100]

    const int tid = threadIdx.x;  // 160
    const int d0  = blockIdx.x * FC_ROWS;

    for (int idx = tid; idx < FF * HH; idx += 160) {
        int f = idx / HH, h = idx % HH;
        fcWs[f * FC_WPAD + h] = fcW[idx];
    }
    for (int idx = tid; idx < FC_ROWS * HH; idx += 160) {
        int r = idx / HH, h = idx % HH;
        hs[r * HH + h] = g_Hs[(size_t)(d0 + r) * HH + h];
    }
    __syncthreads();

    if (tid < 150) {
        const int rg = tid / 75;
        const int f  = 2 * (tid % 75);
        float2 acc[2][8];
        #pragma unroll
        for (int a = 0; a < 2; a++)
            #pragma unroll
            for (int r = 0; r < 8; r++) acc[a][r] = make_float2(0.f, 0.f);

        #pragma unroll
        for (int h2 = 0; h2 < 50; h2++) {
            float2 wa = *reinterpret_cast<const float2*>(&fcWs[f * FC_WPAD + 2 * h2]);
            float2 wb = *reinterpret_cast<const float2*>(&fcWs[(f + 1) * FC_WPAD + 2 * h2]);
            #pragma unroll
            for (int r = 0; r < 8; r++) {
                float2 hv = *reinterpret_cast<const float2*>(&hs[(rg * 8 + r) * HH + 2 * h2]);
                ffma2(acc[0][r], wa, hv);
                ffma2(acc[1][r], wb, hv);
            }
        }

        float b0 = fcb[f], b1 = fcb[f + 1];
        int c = f / 50, rr = f % 50;
        #pragma unroll
        for (int r = 0; r < 8; r++) {
            int d = d0 + rg * 8 + r;
            int n = d & 511;
            int t = (d >> 9) + 1;
            float2 o = make_float2(acc[0][r].x + acc[0][r].y + b0,
                                   acc[1][r].x + acc[1][r].y + b1);
            *reinterpret_cast<float2*>(&out[(size_t)n * XSTR_N + c * XSTR_C + t * XSTR_T + rr]) = o;
        }
    }
}

// ---------------- launch ----------------
extern "C" void kernel_launch(void* const* d_in, const int* in_sizes, int n_in,
                              void* d_out, int out_size) {
    const float* x       = (const float*)d_in[0];
    const float* encWih  = (const float*)d_in[1];
    const float* encWhh  = (const float*)d_in[2];
    const float* encbih  = (const float*)d_in[3];
    const float* encbhh  = (const float*)d_in[4];
    const float* decWih  = (const float*)d_in[5];
    const float* decWhh  = (const float*)d_in[6];
    const float* decbih  = (const float*)d_in[7];
    const float* decbhh  = (const float*)d_in[8];
    const float* fcW     = (const float*)d_in[9];
    const float* fcb     = (const float*)d_in[10];
    float* out = (float*)d_out;
    (void)in_sizes; (void)n_in; (void)out_size;

    cudaFuncSetAttribute(xproj_kernel, cudaFuncAttributeMaxDynamicSharedMemorySize, XP_SMEM);
    cudaFuncSetAttribute(fc_kernel,    cudaFuncAttributeMaxDynamicSharedMemorySize, FC_SMEM);

    prep_misc_kernel<<<G4, 160>>>(encWih, encbih, encbhh, decWih, decbih, decbhh, fcb);
    prep_wd_kernel<<<G4, 128>>>(decWih, decWhh, fcW);

    xproj_kernel<<<(TT * NPTS) / XP_NT, 256, XP_SMEM>>>(x);           // 3840 blocks
    recur_kernel<<<NPTS / 4, 416>>>(encWhh, decWhh);                  // 128 blocks, 1 wave
    zero_t0_kernel<<<(NPTS * FF + 255) / 256, 256>>>(out);
    fc_kernel<<<((TT - 1) * NPTS) / FC_ROWS, 160, FC_SMEM>>>(fcW, fcb, out);  // 9568 blocks
}

// round 4
// speedup vs baseline: 1.0725x; 1.0725x over previous
#include <cuda_runtime.h>
#include <cuda_bf16.h>
#include <cstdint>

// ---------------- problem constants ----------------
#define NPTS   512            // batch N
#define TT     300            // time steps
#define FF     150            // feature dim
#define HH     100            // hidden dim
#define G4     400            // 4*H gate rows
// x layout strides (floats): x[n][c][t][v][m], C=3,V=25,M=2
#define XSTR_N 45000
#define XSTR_C 15000
#define XSTR_T 50

// ---------------- scratch (device globals; no allocs allowed) ----------------
__device__ float g_Xp[(size_t)TT * NPTS * G4];       // encoder pre-activations (+bias)
__device__ float g_Hs[(size_t)(TT - 1) * NPTS * HH]; // decoder hidden states
__device__ float g_Wt[FF * G4];                      // enc_Wih transposed [f][g]
__device__ float g_Wd[G4 * HH];                      // folded decoder recurrent matrix
__device__ float g_biase[G4];
__device__ float g_bias0[G4];
__device__ float g_biasd[G4];

// ---------------- helpers ----------------
__device__ __forceinline__ void ffma2(float2& c, const float2& a, const float2& b) {
    asm("fma.rn.f32x2 %0, %1, %2, %0;"
        : "+l"(reinterpret_cast<unsigned long long&>(c))
        : "l"(reinterpret_cast<const unsigned long long&>(a)),
          "l"(reinterpret_cast<const unsigned long long&>(b)));
}

__device__ __forceinline__ float sigm(float x) {
    return __fdividef(1.0f, 1.0f + __expf(-x));
}
__device__ __forceinline__ float tanh_(float x) {
    return __fdividef(2.0f, 1.0f + __expf(-2.0f * x)) - 1.0f;
}

// ---------------- prep 1: transpose enc_Wih, build biases ----------------
__global__ void prep_misc_kernel(const float* __restrict__ encWih,
                                 const float* __restrict__ encbih,
                                 const float* __restrict__ encbhh,
                                 const float* __restrict__ decWih,
                                 const float* __restrict__ decbih,
                                 const float* __restrict__ decbhh,
                                 const float* __restrict__ fcb) {
    const int gg  = blockIdx.x;   // gate row 0..399
    const int tid = threadIdx.x;  // 160 threads
    if (tid < FF) g_Wt[tid * G4 + gg] = encWih[gg * FF + tid];
    __shared__ float red[160];
    red[tid] = (tid < FF) ? decWih[gg * FF + tid] * fcb[tid] : 0.0f;
    __syncthreads();
    if (tid == 0) {
        float sum = 0.0f;
        for (int f = 0; f < FF; f++) sum += red[f];
        g_biase[gg] = encbih[gg] + encbhh[gg];
        float b0 = decbih[gg] + decbhh[gg];
        g_bias0[gg] = b0;
        g_biasd[gg] = b0 + sum;
    }
}

// ---------------- prep 2: Wd = dec_Whh + dec_Wih @ fc_W ----------------
__global__ void prep_wd_kernel(const float* __restrict__ decWih,
                               const float* __restrict__ decWhh,
                               const float* __restrict__ fcW) {
    const int gg = blockIdx.x;   // 0..399
    const int h  = threadIdx.x;  // 128 threads
    if (h < HH) {
        float acc = decWhh[gg * HH + h];
        for (int f = 0; f < FF; f++)
            acc += decWih[gg * FF + f] * fcW[f * HH + h];
        g_Wd[gg * HH + h] = acc;
    }
}

// ---------------- xproj: Xp[t*512+n][g] = xs[n,t,:] @ enc_Wih[g,:].T + biase[g] ----------------
#define XP_NT   40
#define XP_NTP  41
#define XP_KC   25
#define XP_SMEM (150 * XP_NTP * 8 + XP_KC * G4 * 4)  // 49200 + 40000 = 89200 B

__global__ void __launch_bounds__(256, 2) xproj_kernel(const float* __restrict__ x) {
    extern __shared__ float sm[];
    float2* Adup = reinterpret_cast<float2*>(sm);   // [150][XP_NTP]
    float*  Ws   = sm + 150 * XP_NTP * 2;           // [XP_KC][400]

    const int tid = threadIdx.x;
    const int nt0 = blockIdx.x * XP_NT;

    for (int idx = tid; idx < XP_NT * FF; idx += 256) {
        int row = idx / FF, f = idx % FF;
        int nt = nt0 + row;
        int n = nt & 511, t = nt >> 9;
        float v = x[(size_t)n * XSTR_N + (f / 50) * XSTR_C + t * XSTR_T + (f % 50)];
        Adup[f * XP_NTP + row] = make_float2(v, v);
    }

    const bool act = tid < 250;
    const int gi = tid % 25;
    const int ni = tid / 25;

    float2 acc[4][8];
    #pragma unroll
    for (int r = 0; r < 4; r++)
        #pragma unroll
        for (int j = 0; j < 8; j++) acc[r][j] = make_float2(0.f, 0.f);

    for (int kc = 0; kc < FF; kc += XP_KC) {
        __syncthreads();
        for (int idx = tid; idx < XP_KC * G4; idx += 256)
            Ws[idx] = g_Wt[kc * G4 + idx];
        __syncthreads();
        if (act) {
            #pragma unroll
            for (int k = 0; k < XP_KC; k++) {
                float2 a0 = Adup[(kc + k) * XP_NTP + ni * 4 + 0];
                float2 a1 = Adup[(kc + k) * XP_NTP + ni * 4 + 1];
                float2 a2 = Adup[(kc + k) * XP_NTP + ni * 4 + 2];
                float2 a3 = Adup[(kc + k) * XP_NTP + ni * 4 + 3];
                #pragma unroll
                for (int j = 0; j < 8; j++) {
                    float2 w = *reinterpret_cast<const float2*>(&Ws[k * G4 + 2 * gi + 50 * j]);
                    ffma2(acc[0][j], a0, w);
                    ffma2(acc[1][j], a1, w);
                    ffma2(acc[2][j], a2, w);
                    ffma2(acc[3][j], a3, w);
                }
            }
        }
    }

    if (act) {
        #pragma unroll
        for (int r = 0; r < 4; r++) {
            size_t base = (size_t)(nt0 + ni * 4 + r) * G4;
            #pragma unroll
            for (int j = 0; j < 8; j++) {
                int gg = 2 * gi + 50 * j;
                float2 o = acc[r][j];
                o.x += g_biase[gg];
                o.y += g_biase[gg + 1];
                *reinterpret_cast<float2*>(&g_Xp[base + gg]) = o;
            }
        }
    }
}

// ---------------- recurrence: 128 CTAs x 4 samples, 599 serial steps ----------------
// 800 threads: lanes 2i/2i+1 share gate g=tid>>1, each holds half the W row
// (13 float4 = 52 regs). Partials combined via shfl.xor(1). Even lane then
// handles samples 0,1; odd lane samples 2,3. h reads are LDS.128 broadcasts.
__global__ void __launch_bounds__(800, 1) recur_kernel(const float* __restrict__ encWhh,
                                                       const float* __restrict__ decWhh) {
    __shared__ __align__(16) float Hsm[4][104];   // padded: h[100..103] = 0
    __shared__ float Gsm[4][G4];

    const int tid   = threadIdx.x;       // 0..799
    const int gate  = tid >> 1;          // 0..399
    const int khalf = tid & 1;           // 0 or 1
    const int b0    = khalf * 13;        // k4-block base (blocks of 4 k's)
    const int s0    = khalf * 2;         // this lane's first sample slot
    const int s1    = s0 + 1;
    const int n0    = blockIdx.x * 4;

    // update-phase mapping (tid < 400)
    const int su = tid / HH;
    const int ju = tid % HH;

    float4 W4[13];
    float creg = 0.0f;

    // init Hsm = 0 including pad (4*104 = 416 floats)
    if (tid < 416) reinterpret_cast<float*>(Hsm)[tid] = 0.0f;

    auto load_w = [&](const float* Wrow) {
        #pragma unroll
        for (int b = 0; b < 13; b++) {
            int k0 = (b0 + b) * 4;
            if (k0 < HH)
                W4[b] = *reinterpret_cast<const float4*>(Wrow + k0);
            else
                W4[b] = make_float4(0.f, 0.f, 0.f, 0.f);
        }
    };

    load_w(encWhh + gate * HH);
    __syncthreads();

    auto step = [&](float x0, float x1, bool store_h, int k) {
        float2 acc[4];
        #pragma unroll
        for (int s = 0; s < 4; s++) acc[s] = make_float2(0.f, 0.f);

        #pragma unroll
        for (int b = 0; b < 13; b++) {
            float4 w = W4[b];
            float2 wlo = make_float2(w.x, w.y);
            float2 whi = make_float2(w.z, w.w);
            const int off = (b0 + b) * 4;
            #pragma unroll
            for (int s = 0; s < 4; s++) {
                float4 h = *reinterpret_cast<const float4*>(&Hsm[s][off]);
                ffma2(acc[s], wlo, make_float2(h.x, h.y));
                ffma2(acc[s], whi, make_float2(h.z, h.w));
            }
        }

        float pv[4];
        #pragma unroll
        for (int s = 0; s < 4; s++) {
            float v = acc[s].x + acc[s].y;
            v += __shfl_xor_sync(0xFFFFFFFFu, v, 1);
            pv[s] = v;
        }

        float pre0 = pv[s0] + x0;
        float pre1 = pv[s1] + x1;
        float a0, a1;
        if (gate >= 200 && gate < 300) { a0 = tanh_(pre0); a1 = tanh_(pre1); }
        else                            { a0 = sigm(pre0);  a1 = sigm(pre1);  }
        Gsm[s0][gate] = a0;
        Gsm[s1][gate] = a1;
        __syncthreads();

        if (tid < G4) {
            float i_ = Gsm[su][ju];
            float f_ = Gsm[su][HH + ju];
            float gg = Gsm[su][2 * HH + ju];
            float o_ = Gsm[su][3 * HH + ju];
            creg = f_ * creg + i_ * gg;
            float hn = o_ * tanh_(creg);
            Hsm[su][ju] = hn;
            if (store_h)
                g_Hs[((size_t)k * NPTS + n0 + su) * HH + ju] = hn;
        }
        __syncthreads();
    };

    // ---- encoder: 300 steps, g_Xp prefetched one step ahead ----
    float px0, px1;
    {
        const float* p = g_Xp + ((size_t)0 * NPTS + n0) * G4 + gate;
        px0 = p[(size_t)s0 * G4];
        px1 = p[(size_t)s1 * G4];
    }
    for (int t = 0; t < TT; t++) {
        float cx0 = px0, cx1 = px1;
        if (t + 1 < TT) {
            const float* p = g_Xp + ((size_t)(t + 1) * NPTS + n0) * G4 + gate;
            px0 = p[(size_t)s0 * G4];
            px1 = p[(size_t)s1 * G4];
        }
        step(cx0, cx1, false, 0);
    }

    // ---- decoder step 0: raw dec_Whh (inp = 0) ----
    load_w(decWhh + gate * HH);
    {
        float b = g_bias0[gate];
        step(b, b, true, 0);
    }

    // ---- decoder steps 1..298: folded Wd ----
    load_w(g_Wd + gate * HH);
    {
        float b = g_biasd[gate];
        for (int k = 1; k < TT - 1; k++)
            step(b, b, true, k);
    }
}

// ---------------- zero out t=0 slice of the output ----------------
__global__ void zero_t0_kernel(float* __restrict__ out) {
    int idx = blockIdx.x * 256 + threadIdx.x;
    if (idx < NPTS * FF) {
        int n = idx / FF, f = idx % FF;
        out[(size_t)n * XSTR_N + (f / 50) * XSTR_C + (f % 50)] = 0.0f;
    }
}

// ---------------- fc: out[t>=1] = Hs @ fc_W.T + fc_b, scattered to (N,C,T,V,M) ----------------
// Block: 32 rows (flat d = k*512+n) x 150 f. 320 threads, 300 active:
//   rg = tid/75 (4 row-groups of 8), f = 2*(tid%75). FFMA2 paired over h.
#define FC_ROWS 32
#define FC_WPAD 102
#define FC_SMEM ((FF * FC_WPAD + FC_ROWS * HH) * 4)  // 61200 + 12800 = 74000 B

__global__ void __launch_bounds__(320, 2) fc_kernel(const float* __restrict__ fcW,
                                                    const float* __restrict__ fcb,
                                                    float* __restrict__ out) {
    extern __shared__ float sm[];
    float* fcWs = sm;                 // [150][FC_WPAD]
    float* hs   = sm + FF * FC_WPAD;  // [32][100]

    const int tid = threadIdx.x;  // 320
    const int d0  = blockIdx.x * FC_ROWS;

    for (int idx = tid; idx < FF * HH; idx += 320) {
        int f = idx / HH, h = idx % HH;
        fcWs[f * FC_WPAD + h] = fcW[idx];
    }
    for (int idx = tid; idx < FC_ROWS * HH; idx += 320) {
        int r = idx / HH, h = idx % HH;
        hs[r * HH + h] = g_Hs[(size_t)(d0 + r) * HH + h];
    }
    __syncthreads();

    if (tid < 300) {
        const int rg = tid / 75;
        const int f  = 2 * (tid % 75);
        float2 acc[2][8];
        #pragma unroll
        for (int a = 0; a < 2; a++)
            #pragma unroll
            for (int r = 0; r < 8; r++) acc[a][r] = make_float2(0.f, 0.f);

        #pragma unroll
        for (int h2 = 0; h2 < 50; h2++) {
            float2 wa = *reinterpret_cast<const float2*>(&fcWs[f * FC_WPAD + 2 * h2]);
            float2 wb = *reinterpret_cast<const float2*>(&fcWs[(f + 1) * FC_WPAD + 2 * h2]);
            #pragma unroll
            for (int r = 0; r < 8; r++) {
                float2 hv = *reinterpret_cast<const float2*>(&hs[(rg * 8 + r) * HH + 2 * h2]);
                ffma2(acc[0][r], wa, hv);
                ffma2(acc[1][r], wb, hv);
            }
        }

        float b0 = fcb[f], b1 = fcb[f + 1];
        int c = f / 50, rr = f % 50;
        #pragma unroll
        for (int r = 0; r < 8; r++) {
            int d = d0 + rg * 8 + r;
            int n = d & 511;
            int t = (d >> 9) + 1;
            float2 o = make_float2(acc[0][r].x + acc[0][r].y + b0,
                                   acc[1][r].x + acc[1][r].y + b1);
            *reinterpret_cast<float2*>(&out[(size_t)n * XSTR_N + c * XSTR_C + t * XSTR_T + rr]) = o;
        }
    }
}

// ---------------- launch ----------------
extern "C" void kernel_launch(void* const* d_in, const int* in_sizes, int n_in,
                              void* d_out, int out_size) {
    const float* x       = (const float*)d_in[0];
    const float* encWih  = (const float*)d_in[1];
    const float* encWhh  = (const float*)d_in[2];
    const float* encbih  = (const float*)d_in[3];
    const float* encbhh  = (const float*)d_in[4];
    const float* decWih  = (const float*)d_in[5];
    const float* decWhh  = (const float*)d_in[6];
    const float* decbih  = (const float*)d_in[7];
    const float* decbhh  = (const float*)d_in[8];
    const float* fcW     = (const float*)d_in[9];
    const float* fcb     = (const float*)d_in[10];
    float* out = (float*)d_out;
    (void)in_sizes; (void)n_in; (void)out_size;

    cudaFuncSetAttribute(xproj_kernel, cudaFuncAttributeMaxDynamicSharedMemorySize, XP_SMEM);
    cudaFuncSetAttribute(fc_kernel,    cudaFuncAttributeMaxDynamicSharedMemorySize, FC_SMEM);

    prep_misc_kernel<<<G4, 160>>>(encWih, encbih, encbhh, decWih, decbih, decbhh, fcb);
    prep_wd_kernel<<<G4, 128>>>(decWih, decWhh, fcW);

    xproj_kernel<<<(TT * NPTS) / XP_NT, 256, XP_SMEM>>>(x);           // 3840 blocks
    recur_kernel<<<NPTS / 4, 800>>>(encWhh, decWhh);                  // 128 blocks, 1 wave
    zero_t0_kernel<<<(NPTS * FF + 255) / 256, 256>>>(out);
    fc_kernel<<<((TT - 1) * NPTS) / FC_ROWS, 320, FC_SMEM>>>(fcW, fcb, out);  // 4784 blocks
}